// round 7
// baseline (speedup 1.0000x reference)
#include <cuda_runtime.h>
#include <cuda_bf16.h>
#include <cstdint>

#define N_NODESC 100000
#define N_EDGESC 1600000
#define HID      128
#define NCLS     10
#define NLAYERS  4
#define NGRAPHS  200
#define BN_EPSF  1e-5f

// ---------------- scratch (device globals; no allocation allowed) ----------
__device__ float d_h   [N_NODESC * HID];
__device__ float d_h2  [N_NODESC * HID];
__device__ float d_m   [N_NODESC * HID];
__device__ float d_agg [N_NODESC * HID];
__device__ float d_y   [N_NODESC * HID];
// bf16 B images, pitch 136 bf16 (272B):
// rows [0,512): W_l^T (128/layer); [512,1024): w_ih interleaved (r,z,n,pad)/hcol;
// rows [1024,1536): w_hh interleaved; [1536,1664): fc1_w
__device__ __align__(1024) __nv_bfloat16 d_bimg[1664 * 136];
__device__ float d_bihp[512];   // interleaved b_ih (pad=0)
__device__ float d_bhhp[512];   // interleaved b_hh
__device__ float d_bnacc[2 * HID];
__device__ float d_pool [NGRAPHS * HID];
__device__ float d_cnt  [NGRAPHS];

// ---------------- helpers ---------------------------------------------------
__device__ __forceinline__ uint32_t smem_u32(const void* p) {
    return (uint32_t)__cvta_generic_to_shared(p);
}

__device__ __forceinline__ void ldmx4(uint32_t r[4], uint32_t addr) {
    asm volatile("ldmatrix.sync.aligned.m8n8.x4.shared.b16 {%0,%1,%2,%3}, [%4];"
                 : "=r"(r[0]), "=r"(r[1]), "=r"(r[2]), "=r"(r[3]) : "r"(addr));
}

__device__ __forceinline__ void mma_bf16(float c[4], const uint32_t a[4], const uint32_t b[2]) {
    asm volatile(
        "mma.sync.aligned.m16n8k16.row.col.f32.bf16.bf16.f32 "
        "{%0,%1,%2,%3}, {%4,%5,%6,%7}, {%8,%9}, {%0,%1,%2,%3};"
        : "+f"(c[0]), "+f"(c[1]), "+f"(c[2]), "+f"(c[3])
        : "r"(a[0]), "r"(a[1]), "r"(a[2]), "r"(a[3]), "r"(b[0]), "r"(b[1]));
}

__device__ __forceinline__ float sigmoidf_(float x) {
    return 1.f / (1.f + __expf(-x));
}

#define PITCHB 272

// ---------------- pack B weights -> bf16 images -----------------------------
__global__ void pack_b_kernel(const float* __restrict__ W,
                              const float* __restrict__ w_ih,
                              const float* __restrict__ w_hh,
                              const float* __restrict__ fc1_w,
                              __nv_bfloat16* __restrict__ bimg)
{
    int idx = blockIdx.x * blockDim.x + threadIdx.x;
    if (idx >= 1664 * 128) return;
    int r = idx >> 7;
    int k = idx & 127;
    float v;
    if (r < 512) {                     // W_l^T: row j of layer l = W[l][:,j]
        int l = r >> 7, j = r & 127;
        v = W[l * HID * HID + k * HID + j];
    } else if (r < 1024) {             // w_ih interleaved
        int rr = r - 512, g = rr & 3, q = rr >> 2;
        v = (g < 3) ? w_ih[(g * HID + q) * HID + k] : 0.f;
    } else if (r < 1536) {             // w_hh interleaved
        int rr = r - 1024, g = rr & 3, q = rr >> 2;
        v = (g < 3) ? w_hh[(g * HID + q) * HID + k] : 0.f;
    } else {
        v = fc1_w[(r - 1536) * HID + k];
    }
    bimg[r * 136 + k] = __float2bfloat16(v);
}

__global__ void pack_bias_kernel(const float* __restrict__ b_ih,
                                 const float* __restrict__ b_hh,
                                 float* __restrict__ bihp, float* __restrict__ bhhp)
{
    int idx = threadIdx.x + blockIdx.x * blockDim.x;
    if (idx >= 512) return;
    int g = idx & 3, q = idx >> 2;
    bihp[idx] = (g < 3) ? b_ih[g * HID + q] : 0.f;
    bhhp[idx] = (g < 3) ? b_hh[g * HID + q] : 0.f;
}

// ---------------- generic bf16 GEMM: 64 rows x 128 cols per CTA -------------
// C[row0:row0+64, colblk*128:+128] = A[*,128] @ Bimg_rows[colblk*128:+128]^T
__global__ __launch_bounds__(256) void gemm64_kernel(
    const float* __restrict__ A, const __nv_bfloat16* __restrict__ Bimg,
    int nrows, float* __restrict__ out, int ld, const float* __restrict__ bias)
{
    extern __shared__ char smem[];
    const int tid  = threadIdx.x;
    const int row0 = blockIdx.y * 64;
    const int colblk = blockIdx.x;

    // A: fp32 -> bf16, 64 x 128, pitch 272B
    for (int i = tid; i < 64 * 32; i += 256) {
        int r = i >> 5, c4 = i & 31;
        int gr = row0 + r;
        float4 v = (gr < nrows)
            ? *reinterpret_cast<const float4*>(A + (size_t)gr * HID + c4 * 4)
            : make_float4(0.f, 0.f, 0.f, 0.f);
        __nv_bfloat162 lo = __float22bfloat162_rn(make_float2(v.x, v.y));
        __nv_bfloat162 hi = __float22bfloat162_rn(make_float2(v.z, v.w));
        uint2 pk; pk.x = *reinterpret_cast<uint32_t*>(&lo);
        pk.y = *reinterpret_cast<uint32_t*>(&hi);
        *reinterpret_cast<uint2*>(smem + r * PITCHB + c4 * 8) = pk;
    }
    // B tile: 128 rows x 272B
    {
        const uint4* src = reinterpret_cast<const uint4*>(
            reinterpret_cast<const char*>(Bimg) + (size_t)colblk * 128 * PITCHB);
        uint4* dst = reinterpret_cast<uint4*>(smem + 64 * PITCHB);
        for (int i = tid; i < 128 * PITCHB / 16; i += 256) dst[i] = src[i];
    }
    __syncthreads();

    const int wid = tid >> 5, lane = tid & 31;
    const int wm = wid & 3, wn = wid >> 2;
    const uint32_t sa = smem_u32(smem);
    const uint32_t sb = sa + 64 * PITCHB;

    float acc[8][4] = {};
    const int a_row = wm * 16 + (lane & 15);
    const int a_koff = (lane >> 4) * 16;
    const int b_row = wn * 64 + ((lane >> 4) & 1) * 8 + (lane & 7);
    const int b_koff = ((lane >> 3) & 1) * 16;

#pragma unroll
    for (int ks = 0; ks < 8; ks++) {
        const int kb = ks * 32;
        uint32_t af[4];
        ldmx4(af, sa + (uint32_t)(a_row * PITCHB + kb + a_koff));
        uint32_t bf[8][2];
#pragma unroll
        for (int p = 0; p < 4; p++) {
            uint32_t r4[4];
            ldmx4(r4, sb + (uint32_t)((b_row + p * 16) * PITCHB + kb + b_koff));
            bf[2*p][0] = r4[0]; bf[2*p][1] = r4[1];
            bf[2*p+1][0] = r4[2]; bf[2*p+1][1] = r4[3];
        }
#pragma unroll
        for (int nt = 0; nt < 8; nt++) mma_bf16(acc[nt], af, bf[nt]);
    }

    const int gid = lane >> 2, t4 = lane & 3;
#pragma unroll
    for (int hh = 0; hh < 2; hh++) {
        int gr = row0 + wm * 16 + gid + hh * 8;
        if (gr >= nrows) continue;
#pragma unroll
        for (int nt = 0; nt < 8; nt++) {
            int gc = colblk * 128 + wn * 64 + nt * 8 + t4 * 2;
            float vx = acc[nt][hh*2], vy = acc[nt][hh*2+1];
            if (bias) { vx += bias[gc]; vy += bias[gc+1]; }
            *reinterpret_cast<float2*>(out + (size_t)gr * ld + gc) = make_float2(vx, vy);
        }
    }
}

// ---------------- fused dual-GEMM + GRU kernel ------------------------------
// colblk c handles hidden cols [32c, 32c+32) for 64 rows:
//   gi = agg @ w_ihI^T, gh = h @ w_hhI^T (interleaved gates r,z,n,pad),
//   then GRU in registers, write h_out only.
#define GSMH  17408
#define GSMBI 34816
#define GSMBH 69632
__global__ __launch_bounds__(256, 2) void gemm_gru_kernel(
    const float* __restrict__ Aagg, const float* __restrict__ Ah,
    const __nv_bfloat16* __restrict__ BihI, const __nv_bfloat16* __restrict__ BhhI,
    int nrows, const float* __restrict__ bihp, const float* __restrict__ bhhp,
    float* __restrict__ h_out)
{
    extern __shared__ char smem[];
    const int tid  = threadIdx.x;
    const int row0 = blockIdx.y * 64;
    const int colblk = blockIdx.x;

    // Load agg and h tiles (fp32 -> bf16, pitch 272B)
    for (int i = tid; i < 64 * 32; i += 256) {
        int r = i >> 5, c4 = i & 31;
        int gr = row0 + r;
        float4 va = (gr < nrows)
            ? *reinterpret_cast<const float4*>(Aagg + (size_t)gr * HID + c4 * 4)
            : make_float4(0.f, 0.f, 0.f, 0.f);
        float4 vh = (gr < nrows)
            ? *reinterpret_cast<const float4*>(Ah + (size_t)gr * HID + c4 * 4)
            : make_float4(0.f, 0.f, 0.f, 0.f);
        __nv_bfloat162 alo = __float22bfloat162_rn(make_float2(va.x, va.y));
        __nv_bfloat162 ahi = __float22bfloat162_rn(make_float2(va.z, va.w));
        __nv_bfloat162 hlo = __float22bfloat162_rn(make_float2(vh.x, vh.y));
        __nv_bfloat162 hhi = __float22bfloat162_rn(make_float2(vh.z, vh.w));
        uint2 pa, ph;
        pa.x = *reinterpret_cast<uint32_t*>(&alo); pa.y = *reinterpret_cast<uint32_t*>(&ahi);
        ph.x = *reinterpret_cast<uint32_t*>(&hlo); ph.y = *reinterpret_cast<uint32_t*>(&hhi);
        *reinterpret_cast<uint2*>(smem + r * PITCHB + c4 * 8) = pa;
        *reinterpret_cast<uint2*>(smem + GSMH + r * PITCHB + c4 * 8) = ph;
    }
    // Load B tiles (colblk'th 128 rows of each interleaved image)
    {
        const uint4* si = reinterpret_cast<const uint4*>(
            reinterpret_cast<const char*>(BihI) + (size_t)colblk * 128 * PITCHB);
        const uint4* sh = reinterpret_cast<const uint4*>(
            reinterpret_cast<const char*>(BhhI) + (size_t)colblk * 128 * PITCHB);
        uint4* di = reinterpret_cast<uint4*>(smem + GSMBI);
        uint4* dh = reinterpret_cast<uint4*>(smem + GSMBH);
        for (int i = tid; i < 128 * PITCHB / 16; i += 256) { di[i] = si[i]; dh[i] = sh[i]; }
    }
    __syncthreads();

    const int wid = tid >> 5, lane = tid & 31;
    const int wm = wid & 3, wn = wid >> 2;
    const uint32_t sa  = smem_u32(smem);
    const uint32_t sh_ = sa + GSMH;
    const uint32_t sbi = sa + GSMBI;
    const uint32_t sbh = sa + GSMBH;

    float acc_i[8][4] = {}, acc_h[8][4] = {};
    const int a_row = wm * 16 + (lane & 15);
    const int a_koff = (lane >> 4) * 16;
    const int b_row = wn * 64 + ((lane >> 4) & 1) * 8 + (lane & 7);
    const int b_koff = ((lane >> 3) & 1) * 16;

#pragma unroll
    for (int ks = 0; ks < 8; ks++) {
        const int kb = ks * 32;
        uint32_t afa[4], afh[4];
        ldmx4(afa, sa  + (uint32_t)(a_row * PITCHB + kb + a_koff));
        ldmx4(afh, sh_ + (uint32_t)(a_row * PITCHB + kb + a_koff));
#pragma unroll
        for (int p = 0; p < 4; p++) {
            uint32_t ri[4], rh[4];
            ldmx4(ri, sbi + (uint32_t)((b_row + p * 16) * PITCHB + kb + b_koff));
            ldmx4(rh, sbh + (uint32_t)((b_row + p * 16) * PITCHB + kb + b_koff));
            uint32_t bi0[2] = {ri[0], ri[1]}, bi1[2] = {ri[2], ri[3]};
            uint32_t bh0[2] = {rh[0], rh[1]}, bh1[2] = {rh[2], rh[3]};
            mma_bf16(acc_i[2*p],   afa, bi0);
            mma_bf16(acc_i[2*p+1], afa, bi1);
            mma_bf16(acc_h[2*p],   afh, bh0);
            mma_bf16(acc_h[2*p+1], afh, bh1);
        }
    }

    // GRU epilogue: even lanes in each pair hold gates (r,z); odd hold (n,pad).
    const int gid = lane >> 2, t4 = lane & 3;
    const bool evn = (t4 & 1) == 0;
#pragma unroll
    for (int nt = 0; nt < 8; nt++) {
#pragma unroll
        for (int hh = 0; hh < 2; hh++) {
            float ir = acc_i[nt][hh*2], iz = acc_i[nt][hh*2+1];
            float hr = acc_h[nt][hh*2], hz = acc_h[nt][hh*2+1];
            float in_n = __shfl_xor_sync(0xffffffffu, ir, 1);  // neighbor c0 = i_n
            float hn_n = __shfl_xor_sync(0xffffffffu, hr, 1);  // neighbor c0 = h_n
            if (evn) {
                int gcol = colblk * 128 + wn * 64 + nt * 8 + t4 * 2;   // gate-0 col
                int q = gcol >> 2;                                      // hidden col
                int gr = row0 + wm * 16 + gid + hh * 8;
                if (gr < nrows) {
                    float rr = sigmoidf_((ir + bihp[gcol])     + (hr + bhhp[gcol]));
                    float zz = sigmoidf_((iz + bihp[gcol + 1]) + (hz + bhhp[gcol + 1]));
                    float hn = hn_n + bhhp[gcol + 2];
                    float nn = tanhf((in_n + bihp[gcol + 2]) + rr * hn);
                    float hv = Ah[(size_t)gr * HID + q];
                    h_out[(size_t)gr * HID + q] = (1.f - zz) * nn + zz * hv;
                }
            }
        }
    }
}

// ---------------- edge scatter-add: agg[dst] += m[src] (vector red) ---------
__global__ void scatter_add_kernel(const float* __restrict__ m,
                                   const int* __restrict__ src,
                                   const int* __restrict__ dst,
                                   float* __restrict__ agg)
{
    int e = (blockIdx.x * blockDim.x + threadIdx.x) >> 5;
    if (e >= N_EDGESC) return;
    int lane = threadIdx.x & 31;
    int s = src[e], d = dst[e];
    float4 v = reinterpret_cast<const float4*>(m + (size_t)s * HID)[lane];
    float* a = agg + (size_t)d * HID + lane * 4;
    asm volatile("red.global.add.v4.f32 [%0], {%1, %2, %3, %4};"
                 :: "l"(a), "f"(v.x), "f"(v.y), "f"(v.z), "f"(v.w) : "memory");
}

// ---------------- batchnorm column stats -----------------------------------
__global__ void bn_stats_kernel(const float* __restrict__ y, float* __restrict__ acc)
{
    int j = threadIdx.x;
    float s = 0.f, s2 = 0.f;
    for (int row = blockIdx.x; row < N_NODESC; row += gridDim.x) {
        float v = y[(size_t)row * HID + j];
        s += v; s2 += v * v;
    }
    atomicAdd(&acc[j], s);
    atomicAdd(&acc[HID + j], s2);
}

// ---------------- normalize + relu + per-graph sum pool --------------------
__global__ void norm_pool_kernel(const float* __restrict__ y,
                                 const int* __restrict__ batch,
                                 const float* __restrict__ acc,
                                 const float* __restrict__ gamma,
                                 const float* __restrict__ beta,
                                 float* __restrict__ pool)
{
    int j = threadIdx.x;
    float mean = acc[j] * (1.f / N_NODESC);
    float var  = acc[HID + j] * (1.f / N_NODESC) - mean * mean;
    float sc = rsqrtf(var + BN_EPSF) * gamma[j];
    float sh = beta[j] - mean * sc;

    int r0 = blockIdx.x * 256;
    int r1 = min(r0 + 256, N_NODESC);
    float av = 0.f;
    int gcur = -1;
    for (int row = r0; row < r1; row++) {
        int g = batch[row];
        float v = y[(size_t)row * HID + j] * sc + sh;
        v = fmaxf(v, 0.f);
        if (g != gcur) {
            if (gcur >= 0) atomicAdd(&pool[gcur * HID + j], av);
            av = 0.f; gcur = g;
        }
        av += v;
    }
    if (gcur >= 0) atomicAdd(&pool[gcur * HID + j], av);
}

__global__ void count_kernel(const int* __restrict__ batch, float* __restrict__ cnt)
{
    int n = blockIdx.x * blockDim.x + threadIdx.x;
    if (n < N_NODESC) atomicAdd(&cnt[batch[n]], 1.0f);
}

// ---------------- head: mean pool -> fc2 -> log_softmax --------------------
__global__ void head_kernel(const float* __restrict__ pool,
                            const float* __restrict__ cnt,
                            const float* __restrict__ w2,
                            const float* __restrict__ b2,
                            float* __restrict__ out)
{
    int g = blockIdx.x;
    int lane = threadIdx.x;
    float invc = 1.f / fmaxf(cnt[g], 1.f);
    float f[4];
#pragma unroll
    for (int i = 0; i < 4; i++) f[i] = pool[g * HID + lane * 4 + i] * invc;

    __shared__ float logits[NCLS];
    for (int c = 0; c < NCLS; c++) {
        float p = 0.f;
#pragma unroll
        for (int i = 0; i < 4; i++) p += f[i] * w2[c * HID + lane * 4 + i];
#pragma unroll
        for (int o = 16; o; o >>= 1) p += __shfl_xor_sync(0xffffffffu, p, o);
        if (lane == 0) logits[c] = p + b2[c];
    }
    __syncwarp();
    if (lane == 0) {
        float mx = -1e30f;
        for (int c = 0; c < NCLS; c++) mx = fmaxf(mx, logits[c]);
        float se = 0.f;
        for (int c = 0; c < NCLS; c++) se += expf(logits[c] - mx);
        float lse = mx + logf(se);
        for (int c = 0; c < NCLS; c++) out[g * NCLS + c] = logits[c] - lse;
    }
}

// ---------------- launch ----------------------------------------------------
extern "C" void kernel_launch(void* const* d_in, const int* in_sizes, int n_in,
                              void* d_out, int out_size)
{
    const float* x      = (const float*)d_in[0];
    const int*   ei     = (const int*)  d_in[1];   // [2, E] int32
    const int*   batch  = (const int*)  d_in[2];
    const float* ggnn_w = (const float*)d_in[3];
    const float* w_ih   = (const float*)d_in[4];
    const float* w_hh   = (const float*)d_in[5];
    const float* b_ih   = (const float*)d_in[6];
    const float* b_hh   = (const float*)d_in[7];
    const float* fc1_w  = (const float*)d_in[8];
    const float* fc1_b  = (const float*)d_in[9];
    const float* gamma  = (const float*)d_in[10];
    const float* beta   = (const float*)d_in[11];
    const float* fc2_w  = (const float*)d_in[12];
    const float* fc2_b  = (const float*)d_in[13];
    float* out = (float*)d_out;

    float *h_, *h2_, *m_, *agg_, *y_, *bihp_, *bhhp_, *bn_, *pool_, *cnt_;
    __nv_bfloat16* bimg_;
    cudaGetSymbolAddress((void**)&h_,    d_h);
    cudaGetSymbolAddress((void**)&h2_,   d_h2);
    cudaGetSymbolAddress((void**)&m_,    d_m);
    cudaGetSymbolAddress((void**)&agg_,  d_agg);
    cudaGetSymbolAddress((void**)&y_,    d_y);
    cudaGetSymbolAddress((void**)&bimg_, d_bimg);
    cudaGetSymbolAddress((void**)&bihp_, d_bihp);
    cudaGetSymbolAddress((void**)&bhhp_, d_bhhp);
    cudaGetSymbolAddress((void**)&bn_,   d_bnacc);
    cudaGetSymbolAddress((void**)&pool_, d_pool);
    cudaGetSymbolAddress((void**)&cnt_,  d_cnt);

    const int NH = N_NODESC * HID;
    const unsigned ROWB = (N_NODESC + 63) / 64;     // 1563
    const int smem_g  = 64 * PITCHB + 128 * PITCHB;  // 52224
    const int smem_gg = GSMBH + 128 * PITCHB;        // 104448
    cudaFuncSetAttribute(gemm64_kernel,
                         cudaFuncAttributeMaxDynamicSharedMemorySize, smem_g);
    cudaFuncSetAttribute(gemm_gru_kernel,
                         cudaFuncAttributeMaxDynamicSharedMemorySize, smem_gg);

    cudaMemcpyAsync(h_, x, (size_t)NH * 4, cudaMemcpyDeviceToDevice);
    pack_b_kernel<<<(1664 * 128 + 255) / 256, 256>>>(ggnn_w, w_ih, w_hh, fc1_w, bimg_);
    pack_bias_kernel<<<2, 256>>>(b_ih, b_hh, bihp_, bhhp_);

    float* cur = h_;
    float* nxt = h2_;
    for (int l = 0; l < NLAYERS; l++) {
        // m = h @ W_l
        gemm64_kernel<<<dim3(1, ROWB), 256, smem_g>>>(
            cur, bimg_ + (size_t)l * 128 * 136, N_NODESC, m_, HID, nullptr);
        // agg = segment_sum(m[src], dst)
        cudaMemsetAsync(agg_, 0, (size_t)NH * 4);
        scatter_add_kernel<<<(N_EDGESC * 32 + 255) / 256, 256>>>(
            m_, ei, ei + N_EDGESC, agg_);
        // h' = GRU(agg, h) fused (gi+gh GEMMs + gates)
        gemm_gru_kernel<<<dim3(4, ROWB), 256, smem_gg>>>(
            agg_, cur, bimg_ + 512 * 136, bimg_ + 1024 * 136,
            N_NODESC, bihp_, bhhp_, nxt);
        float* t = cur; cur = nxt; nxt = t;
    }

    // y = h @ fc1_w^T + fc1_b
    gemm64_kernel<<<dim3(1, ROWB), 256, smem_g>>>(
        cur, bimg_ + 1536 * 136, N_NODESC, y_, HID, fc1_b);

    // batchnorm stats + normalize/relu + pooled sums
    cudaMemsetAsync(bn_, 0, 2 * HID * 4);
    cudaMemsetAsync(pool_, 0, NGRAPHS * HID * 4);
    cudaMemsetAsync(cnt_, 0, NGRAPHS * 4);
    bn_stats_kernel<<<512, 128>>>(y_, bn_);
    count_kernel<<<(N_NODESC + 255) / 256, 256>>>(batch, cnt_);
    norm_pool_kernel<<<(N_NODESC + 255) / 256, 128>>>(
        y_, batch, bn_, gamma, beta, pool_);

    // head
    head_kernel<<<NGRAPHS, 32>>>(pool_, cnt_, fc2_w, fc2_b, out);
}

// round 10
// speedup vs baseline: 1.3532x; 1.3532x over previous
#include <cuda_runtime.h>
#include <cuda_bf16.h>
#include <cstdint>

#define N_NODESC 100000
#define N_EDGESC 1600000
#define HID      128
#define H3       384
#define NCLS     10
#define NLAYERS  4
#define NGRAPHS  200
#define BN_EPSF  1e-5f

// ---------------- scratch (device globals; no allocation allowed) ----------
__device__ float d_h   [N_NODESC * HID];
__device__ float d_m   [N_NODESC * HID];
__device__ float d_agg [N_NODESC * HID];
__device__ float d_gi  [N_NODESC * H3];
__device__ float d_gh  [N_NODESC * H3];
__device__ float d_y   [N_NODESC * HID];
// bf16 B images, row pitch 136 bf16 (272B): 2048 rows fused layers, 384 w_ih, 128 fc1
__device__ __align__(1024) __nv_bfloat16 d_bimg[2560 * 136];
__device__ float d_bnacc[2 * HID];
__device__ float d_pool [NGRAPHS * HID];
__device__ float d_cnt  [NGRAPHS];
// CSR scratch
__device__ int d_deg   [N_NODESC];       // degree, then reused as cursor
__device__ int d_rowptr[N_NODESC + 1];
__device__ int d_csrsrc[N_EDGESC];

// ---------------- helpers ---------------------------------------------------
__device__ __forceinline__ uint32_t smem_u32(const void* p) {
    return (uint32_t)__cvta_generic_to_shared(p);
}

__device__ __forceinline__ void ldmx4(uint32_t r[4], uint32_t addr) {
    asm volatile("ldmatrix.sync.aligned.m8n8.x4.shared.b16 {%0,%1,%2,%3}, [%4];"
                 : "=r"(r[0]), "=r"(r[1]), "=r"(r[2]), "=r"(r[3]) : "r"(addr));
}

__device__ __forceinline__ void mma_bf16(float c[4], const uint32_t a[4], const uint32_t b[2]) {
    asm volatile(
        "mma.sync.aligned.m16n8k16.row.col.f32.bf16.bf16.f32 "
        "{%0,%1,%2,%3}, {%4,%5,%6,%7}, {%8,%9}, {%0,%1,%2,%3};"
        : "+f"(c[0]), "+f"(c[1]), "+f"(c[2]), "+f"(c[3])
        : "r"(a[0]), "r"(a[1]), "r"(a[2]), "r"(a[3]), "r"(b[0]), "r"(b[1]));
}

#define PITCHB 272

// ---------------- pack B weights -> bf16 image, pitch 136 -------------------
__global__ void pack_b_kernel(const float* __restrict__ W,
                              const float* __restrict__ w_hh,
                              const float* __restrict__ w_ih,
                              const float* __restrict__ fc1_w,
                              __nv_bfloat16* __restrict__ bimg)
{
    int idx = blockIdx.x * blockDim.x + threadIdx.x;
    if (idx >= 2560 * 128) return;
    int r = idx >> 7;
    int k = idx & 127;
    float v;
    if (r < 2048) {
        int l = r >> 9, rr = r & 511;
        v = (rr < HID) ? W[l * HID * HID + k * HID + rr]
                       : w_hh[(rr - HID) * HID + k];
    } else if (r < 2432) {
        v = w_ih[(r - 2048) * HID + k];
    } else {
        v = fc1_w[(r - 2432) * HID + k];
    }
    bimg[r * 136 + k] = __float2bfloat16(v);
}

// ---------------- bf16 tensor-core GEMM (R6, known-good) --------------------
#define SMB_OFF 34816
__global__ __launch_bounds__(256) void gemm_bf16_kernel(
    const float* __restrict__ A, const __nv_bfloat16* __restrict__ Bimg,
    int nrows,
    float* __restrict__ out0, int ld0, const float* __restrict__ bias0,
    int split, float* __restrict__ out1, int ld1, const float* __restrict__ bias1)
{
    extern __shared__ char smem[];
    const int tid    = threadIdx.x;
    const int row0   = blockIdx.y * 128;
    const int colblk = blockIdx.x;

    for (int i = tid; i < 128 * 32; i += 256) {
        int r = i >> 5, c4 = i & 31;
        int gr = row0 + r;
        float4 v = (gr < nrows)
            ? *reinterpret_cast<const float4*>(A + (size_t)gr * HID + c4 * 4)
            : make_float4(0.f, 0.f, 0.f, 0.f);
        __nv_bfloat162 lo = __float22bfloat162_rn(make_float2(v.x, v.y));
        __nv_bfloat162 hi = __float22bfloat162_rn(make_float2(v.z, v.w));
        uint2 pk;
        pk.x = *reinterpret_cast<uint32_t*>(&lo);
        pk.y = *reinterpret_cast<uint32_t*>(&hi);
        *reinterpret_cast<uint2*>(smem + r * PITCHB + c4 * 8) = pk;
    }
    {
        const uint4* src = reinterpret_cast<const uint4*>(
            reinterpret_cast<const char*>(Bimg) + (size_t)colblk * 128 * PITCHB);
        uint4* dst = reinterpret_cast<uint4*>(smem + SMB_OFF);
        for (int i = tid; i < 128 * PITCHB / 16; i += 256) dst[i] = src[i];
    }
    __syncthreads();

    const int wid  = tid >> 5;
    const int lane = tid & 31;
    const int wm = wid & 3;
    const int wn = wid >> 2;
    const uint32_t sa  = smem_u32(smem);
    const uint32_t sbB = sa + SMB_OFF;

    float acc[2][8][4] = {};

    const int a_row  = wm * 32 + (lane & 15);
    const int a_koff = (lane >> 4) * 16;
    const int b_row  = wn * 64 + ((lane >> 4) & 1) * 8 + (lane & 7);
    const int b_koff = ((lane >> 3) & 1) * 16;

#pragma unroll
    for (int ks = 0; ks < 8; ks++) {
        const int kb = ks * 32;
        uint32_t af[2][4];
#pragma unroll
        for (int mt = 0; mt < 2; mt++)
            ldmx4(af[mt], sa + (uint32_t)((a_row + mt * 16) * PITCHB + kb + a_koff));
        uint32_t bf[8][2];
#pragma unroll
        for (int p = 0; p < 4; p++) {
            uint32_t r4[4];
            ldmx4(r4, sbB + (uint32_t)((b_row + p * 16) * PITCHB + kb + b_koff));
            bf[2 * p][0] = r4[0]; bf[2 * p][1] = r4[1];
            bf[2 * p + 1][0] = r4[2]; bf[2 * p + 1][1] = r4[3];
        }
#pragma unroll
        for (int mt = 0; mt < 2; mt++)
#pragma unroll
            for (int nt = 0; nt < 8; nt++)
                mma_bf16(acc[mt][nt], af[mt], bf[nt]);
    }

    const int gid = lane >> 2, t4 = lane & 3;
#pragma unroll
    for (int mt = 0; mt < 2; mt++) {
#pragma unroll
        for (int hh = 0; hh < 2; hh++) {
            int gr = row0 + wm * 32 + mt * 16 + gid + hh * 8;
            if (gr >= nrows) continue;
#pragma unroll
            for (int nt = 0; nt < 8; nt++) {
                int gc = colblk * 128 + wn * 64 + nt * 8 + t4 * 2;
                float vx = acc[mt][nt][hh * 2 + 0];
                float vy = acc[mt][nt][hh * 2 + 1];
                if (gc < split) {
                    if (bias0) { vx += bias0[gc]; vy += bias0[gc + 1]; }
                    *reinterpret_cast<float2*>(out0 + (size_t)gr * ld0 + gc) =
                        make_float2(vx, vy);
                } else {
                    int c1 = gc - split;
                    if (bias1) { vx += bias1[c1]; vy += bias1[c1 + 1]; }
                    *reinterpret_cast<float2*>(out1 + (size_t)gr * ld1 + c1) =
                        make_float2(vx, vy);
                }
            }
        }
    }
}

// ---------------- CSR build (once per launch) -------------------------------
__global__ __launch_bounds__(256) void deg_kernel(const int* __restrict__ dst,
                                                  int* __restrict__ deg)
{
    int e = blockIdx.x * blockDim.x + threadIdx.x;
    if (e < N_EDGESC) atomicAdd(&deg[dst[e]], 1);
}

// single-block exclusive scan over 100000 degrees -> rowptr[0..N]
#define SCAN_T 512
__global__ __launch_bounds__(SCAN_T) void scan_kernel(const int* __restrict__ deg,
                                                      int* __restrict__ rowptr)
{
    __shared__ int part[SCAN_T];
    const int tid = threadIdx.x;
    const int CH = (N_NODESC + SCAN_T - 1) / SCAN_T;   // 196
    int base = tid * CH;
    int s = 0;
    for (int i = 0; i < CH; i++) {
        int idx = base + i;
        if (idx < N_NODESC) s += deg[idx];
    }
    part[tid] = s;
    __syncthreads();
    for (int off = 1; off < SCAN_T; off <<= 1) {
        int v = (tid >= off) ? part[tid - off] : 0;
        __syncthreads();
        part[tid] += v;
        __syncthreads();
    }
    int run = (tid == 0) ? 0 : part[tid - 1];
    for (int i = 0; i < CH; i++) {
        int idx = base + i;
        if (idx < N_NODESC) { rowptr[idx] = run; run += deg[idx]; }
    }
    if (tid == SCAN_T - 1) rowptr[N_NODESC] = part[SCAN_T - 1];
}

__global__ __launch_bounds__(256) void fill_kernel(
    const int* __restrict__ src, const int* __restrict__ dst,
    const int* __restrict__ rowptr, int* __restrict__ cursor,
    int* __restrict__ csrsrc)
{
    int e = blockIdx.x * blockDim.x + threadIdx.x;
    if (e >= N_EDGESC) return;
    int d = dst[e];
    int pos = rowptr[d] + atomicAdd(&cursor[d], 1);
    csrsrc[pos] = src[e];
}

// ---------------- CSR gather aggregation: agg[n] = sum_{e: dst=n} m[src_e] --
__global__ __launch_bounds__(256) void aggregate_kernel(
    const float* __restrict__ m,
    const int* __restrict__ rowptr,
    const int* __restrict__ csrsrc,
    float* __restrict__ agg)
{
    int n = (blockIdx.x * blockDim.x + threadIdx.x) >> 5;
    if (n >= N_NODESC) return;
    int lane = threadIdx.x & 31;
    int beg = rowptr[n], end = rowptr[n + 1];
    float4 acc = make_float4(0.f, 0.f, 0.f, 0.f);
    int i = beg;
    for (; i + 4 <= end; i += 4) {
        int s0 = csrsrc[i], s1 = csrsrc[i + 1], s2 = csrsrc[i + 2], s3 = csrsrc[i + 3];
        float4 v0 = reinterpret_cast<const float4*>(m + (size_t)s0 * HID)[lane];
        float4 v1 = reinterpret_cast<const float4*>(m + (size_t)s1 * HID)[lane];
        float4 v2 = reinterpret_cast<const float4*>(m + (size_t)s2 * HID)[lane];
        float4 v3 = reinterpret_cast<const float4*>(m + (size_t)s3 * HID)[lane];
        acc.x += v0.x + v1.x + v2.x + v3.x;
        acc.y += v0.y + v1.y + v2.y + v3.y;
        acc.z += v0.z + v1.z + v2.z + v3.z;
        acc.w += v0.w + v1.w + v2.w + v3.w;
    }
    for (; i < end; i++) {
        int s = csrsrc[i];
        float4 v = reinterpret_cast<const float4*>(m + (size_t)s * HID)[lane];
        acc.x += v.x; acc.y += v.y; acc.z += v.z; acc.w += v.w;
    }
    reinterpret_cast<float4*>(agg + (size_t)n * HID)[lane] = acc;
}

// ---------------- GRU gate fuse (float4) ------------------------------------
__global__ __launch_bounds__(256) void gru_gate_kernel(
    float* __restrict__ h,
    const float* __restrict__ gi,
    const float* __restrict__ gh)
{
    int idx = blockIdx.x * blockDim.x + threadIdx.x;
    if (idx >= N_NODESC * 32) return;
    int n = idx >> 5, q = idx & 31;
    const float4* gi4 = reinterpret_cast<const float4*>(gi + (size_t)n * H3);
    const float4* gh4 = reinterpret_cast<const float4*>(gh + (size_t)n * H3);
    float4* h4 = reinterpret_cast<float4*>(h + (size_t)n * HID);
    float4 ir = gi4[q], iz = gi4[32 + q], in_ = gi4[64 + q];
    float4 hr = gh4[q], hz = gh4[32 + q], hn  = gh4[64 + q];
    float4 hv = h4[q];
    float4 o;
    { float r = 1.f/(1.f+__expf(-(ir.x+hr.x))); float z = 1.f/(1.f+__expf(-(iz.x+hz.x)));
      float nn = tanhf(in_.x + r*hn.x); o.x = (1.f-z)*nn + z*hv.x; }
    { float r = 1.f/(1.f+__expf(-(ir.y+hr.y))); float z = 1.f/(1.f+__expf(-(iz.y+hz.y)));
      float nn = tanhf(in_.y + r*hn.y); o.y = (1.f-z)*nn + z*hv.y; }
    { float r = 1.f/(1.f+__expf(-(ir.z+hr.z))); float z = 1.f/(1.f+__expf(-(iz.z+hz.z)));
      float nn = tanhf(in_.z + r*hn.z); o.z = (1.f-z)*nn + z*hv.z; }
    { float r = 1.f/(1.f+__expf(-(ir.w+hr.w))); float z = 1.f/(1.f+__expf(-(iz.w+hz.w)));
      float nn = tanhf(in_.w + r*hn.w); o.w = (1.f-z)*nn + z*hv.w; }
    h4[q] = o;
}

// ---------------- batchnorm column stats -----------------------------------
__global__ __launch_bounds__(128) void bn_stats_kernel(const float* __restrict__ y,
                                                       float* __restrict__ acc)
{
    int j = threadIdx.x;
    float s = 0.f, s2 = 0.f;
    for (int row = blockIdx.x; row < N_NODESC; row += gridDim.x) {
        float v = y[(size_t)row * HID + j];
        s += v; s2 += v * v;
    }
    atomicAdd(&acc[j], s);
    atomicAdd(&acc[HID + j], s2);
}

// ---------------- normalize + relu + per-graph sum pool --------------------
__global__ __launch_bounds__(128) void norm_pool_kernel(
    const float* __restrict__ y,
    const int* __restrict__ batch,
    const float* __restrict__ acc,
    const float* __restrict__ gamma,
    const float* __restrict__ beta,
    float* __restrict__ pool)
{
    int j = threadIdx.x;
    float mean = acc[j] * (1.f / N_NODESC);
    float var  = acc[HID + j] * (1.f / N_NODESC) - mean * mean;
    float sc = rsqrtf(var + BN_EPSF) * gamma[j];
    float sh = beta[j] - mean * sc;

    int r0 = blockIdx.x * 256;
    int r1 = min(r0 + 256, N_NODESC);
    float av = 0.f;
    int gcur = -1;
    for (int row = r0; row < r1; row++) {
        int g = batch[row];
        float v = y[(size_t)row * HID + j] * sc + sh;
        v = fmaxf(v, 0.f);
        if (g != gcur) {
            if (gcur >= 0) atomicAdd(&pool[gcur * HID + j], av);
            av = 0.f; gcur = g;
        }
        av += v;
    }
    if (gcur >= 0) atomicAdd(&pool[gcur * HID + j], av);
}

__global__ __launch_bounds__(256) void count_kernel(const int* __restrict__ batch,
                                                    float* __restrict__ cnt)
{
    int n = blockIdx.x * blockDim.x + threadIdx.x;
    if (n < N_NODESC) atomicAdd(&cnt[batch[n]], 1.0f);
}

// ---------------- head: mean pool -> fc2 -> log_softmax --------------------
__global__ __launch_bounds__(32) void head_kernel(
    const float* __restrict__ pool,
    const float* __restrict__ cnt,
    const float* __restrict__ w2,
    const float* __restrict__ b2,
    float* __restrict__ out)
{
    int g = blockIdx.x;
    int lane = threadIdx.x;
    float invc = 1.f / fmaxf(cnt[g], 1.f);
    float f[4];
#pragma unroll
    for (int i = 0; i < 4; i++) f[i] = pool[g * HID + lane * 4 + i] * invc;

    __shared__ float logits[NCLS];
    for (int c = 0; c < NCLS; c++) {
        float p = 0.f;
#pragma unroll
        for (int i = 0; i < 4; i++) p += f[i] * w2[c * HID + lane * 4 + i];
#pragma unroll
        for (int o = 16; o; o >>= 1) p += __shfl_xor_sync(0xffffffffu, p, o);
        if (lane == 0) logits[c] = p + b2[c];
    }
    __syncwarp();
    if (lane == 0) {
        float mx = -1e30f;
        for (int c = 0; c < NCLS; c++) mx = fmaxf(mx, logits[c]);
        float se = 0.f;
        for (int c = 0; c < NCLS; c++) se += expf(logits[c] - mx);
        float lse = mx + logf(se);
        for (int c = 0; c < NCLS; c++) out[g * NCLS + c] = logits[c] - lse;
    }
}

// ---------------- launch ----------------------------------------------------
extern "C" void kernel_launch(void* const* d_in, const int* in_sizes, int n_in,
                              void* d_out, int out_size)
{
    const float* x      = (const float*)d_in[0];
    const int*   ei     = (const int*)  d_in[1];   // [2, E] int32
    const int*   batch  = (const int*)  d_in[2];
    const float* ggnn_w = (const float*)d_in[3];
    const float* w_ih   = (const float*)d_in[4];
    const float* w_hh   = (const float*)d_in[5];
    const float* b_ih   = (const float*)d_in[6];
    const float* b_hh   = (const float*)d_in[7];
    const float* fc1_w  = (const float*)d_in[8];
    const float* fc1_b  = (const float*)d_in[9];
    const float* gamma  = (const float*)d_in[10];
    const float* beta   = (const float*)d_in[11];
    const float* fc2_w  = (const float*)d_in[12];
    const float* fc2_b  = (const float*)d_in[13];
    float* out = (float*)d_out;

    float *h_, *m_, *agg_, *gi_, *gh_, *y_, *bn_, *pool_, *cnt_;
    int *deg_, *rowptr_, *csrsrc_;
    __nv_bfloat16* bimg_;
    cudaGetSymbolAddress((void**)&h_,     d_h);
    cudaGetSymbolAddress((void**)&m_,     d_m);
    cudaGetSymbolAddress((void**)&agg_,   d_agg);
    cudaGetSymbolAddress((void**)&gi_,    d_gi);
    cudaGetSymbolAddress((void**)&gh_,    d_gh);
    cudaGetSymbolAddress((void**)&y_,     d_y);
    cudaGetSymbolAddress((void**)&bimg_,  d_bimg);
    cudaGetSymbolAddress((void**)&bn_,    d_bnacc);
    cudaGetSymbolAddress((void**)&pool_,  d_pool);
    cudaGetSymbolAddress((void**)&cnt_,   d_cnt);
    cudaGetSymbolAddress((void**)&deg_,   d_deg);
    cudaGetSymbolAddress((void**)&rowptr_, d_rowptr);
    cudaGetSymbolAddress((void**)&csrsrc_, d_csrsrc);

    const int NH = N_NODESC * HID;
    const unsigned ROWB = (N_NODESC + 127) / 128;   // 782
    const int smem_bytes = 2 * 34816;               // 69632
    cudaFuncSetAttribute(gemm_bf16_kernel,
                         cudaFuncAttributeMaxDynamicSharedMemorySize, smem_bytes);

    // init: h = x ; pack bf16 B images ; build CSR (once — edges invariant)
    cudaMemcpyAsync(h_, x, (size_t)NH * 4, cudaMemcpyDeviceToDevice);
    pack_b_kernel<<<(2560 * 128 + 255) / 256, 256>>>(ggnn_w, w_hh, w_ih, fc1_w, bimg_);
    cudaMemsetAsync(deg_, 0, N_NODESC * 4);
    deg_kernel<<<(N_EDGESC + 255) / 256, 256>>>(ei + N_EDGESC, deg_);
    scan_kernel<<<1, SCAN_T>>>(deg_, rowptr_);
    cudaMemsetAsync(deg_, 0, N_NODESC * 4);   // reuse as cursor
    fill_kernel<<<(N_EDGESC + 255) / 256, 256>>>(ei, ei + N_EDGESC, rowptr_, deg_, csrsrc_);

    for (int l = 0; l < NLAYERS; l++) {
        // fused: [m | gh] = h @ [W_l^T ; w_hh]^T
        gemm_bf16_kernel<<<dim3(4, ROWB), 256, smem_bytes>>>(
            h_, bimg_ + (size_t)l * 512 * 136, N_NODESC,
            m_, HID, nullptr, HID, gh_, H3, b_hh);
        // agg = segment_sum(m[src], dst) via CSR gather (no atomics, no memset)
        aggregate_kernel<<<(N_NODESC * 32 + 255) / 256, 256>>>(m_, rowptr_, csrsrc_, agg_);
        // gi = agg @ w_ih^T + b_ih
        gemm_bf16_kernel<<<dim3(3, ROWB), 256, smem_bytes>>>(
            agg_, bimg_ + 2048 * 136, N_NODESC,
            gi_, H3, b_ih, 1 << 30, nullptr, 0, nullptr);
        // h = GRU(agg, h)
        gru_gate_kernel<<<(N_NODESC * 32 + 255) / 256, 256>>>(h_, gi_, gh_);
    }

    // y = h @ fc1_w^T + fc1_b
    gemm_bf16_kernel<<<dim3(1, ROWB), 256, smem_bytes>>>(
        h_, bimg_ + 2432 * 136, N_NODESC,
        y_, HID, fc1_b, 1 << 30, nullptr, 0, nullptr);

    // batchnorm stats + normalize/relu + pooled sums
    cudaMemsetAsync(bn_, 0, 2 * HID * 4);
    cudaMemsetAsync(pool_, 0, NGRAPHS * HID * 4);
    cudaMemsetAsync(cnt_, 0, NGRAPHS * 4);
    bn_stats_kernel<<<512, 128>>>(y_, bn_);
    count_kernel<<<(N_NODESC + 255) / 256, 256>>>(batch, cnt_);
    norm_pool_kernel<<<(N_NODESC + 255) / 256, 128>>>(
        y_, batch, bn_, gamma, beta, pool_);

    // head
    head_kernel<<<NGRAPHS, 32>>>(pool_, cnt_, fc2_w, fc2_b, out);
}